// round 3
// baseline (speedup 1.0000x reference)
#include <cuda_runtime.h>
#include <cuda_bf16.h>

// RaycastOcc: out[b,0,h,w] = max over 120 ray steps of occ3d[b,0,iz,iy,ix].
// CRITICAL: samples sit exactly on voxel boundaries (p_z = 50*d, d = 0.1+0.02k),
// so floor() is decided by last-ulp rounding. We replicate the reference's
// arithmetic order exactly with IEEE _rn intrinsics and NO fma:
//   d    = fl(0.1f + fl(0.02f * k))
//   cam  = fl(dir * d)
//   p_i  = fl( fl(fl(Ri0*camx) + fl(Ri1*camy)) + fl(Ri2*camz) ) + t_i   (rounded add)
//   idx  = floor(p)

#define DZV 128
#define DYV 128
#define DXV 256
#define HH  256
#define WW  320
#define BB  8
#define NSTEP 120
#define DEPTH_MIN 0.1f
#define RAY_INC   0.02f

__global__ __launch_bounds__(256, 8)
void raycast_occ_kernel(const float* __restrict__ occ,
                        const float* __restrict__ vm,
                        const float* __restrict__ intr,
                        float* __restrict__ out)
{
    const int w = blockIdx.x * 32 + threadIdx.x;   // warp = 32 consecutive w
    const int h = blockIdx.y * 8  + threadIdx.y;
    const int b = blockIdx.z;

    const float fx = __ldg(intr + 0);
    const float fy = __ldg(intr + 1);
    const float cx = __ldg(intr + 2);
    const float cy = __ldg(intr + 3);

    const float* M = vm + b * 16;
    const float R00 = __ldg(M + 0), R01 = __ldg(M + 1), R02 = __ldg(M + 2),  t0 = __ldg(M + 3);
    const float R10 = __ldg(M + 4), R11 = __ldg(M + 5), R12 = __ldg(M + 6),  t1 = __ldg(M + 7);
    const float R20 = __ldg(M + 8), R21 = __ldg(M + 9), R22 = __ldg(M + 10), t2 = __ldg(M + 11);

    // dirx = ((w + 0.5) - cx) / fx   — each op individually rounded (matches jnp)
    const float dirx = __fdiv_rn(__fadd_rn(__fadd_rn((float)w, 0.5f), -cx), fx);
    const float diry = __fdiv_rn(__fadd_rn(__fadd_rn((float)h, 0.5f), -cy), fy);
    // dirz = 1, so camz = fl(1*d) = d exactly.

    const float* ob = occ + (size_t)b * (DZV * DYV * DXV);

    bool hit = false;

    #pragma unroll 1
    for (int k0 = 0; k0 < NSTEP; k0 += 8) {
        const float kb = (float)k0;
        #pragma unroll
        for (int j = 0; j < 8; ++j) {
            const float kf = __fadd_rn(kb, (float)j);          // exact integer add
            const float d  = __fadd_rn(DEPTH_MIN, __fmul_rn(RAY_INC, kf)); // separate rounds!

            const float camx = __fmul_rn(dirx, d);
            const float camy = __fmul_rn(diry, d);
            const float camz = d;

            // contraction: ((R_i0*camx + R_i1*camy) + R_i2*camz), then + t_i
            const float px = __fadd_rn(
                __fadd_rn(__fadd_rn(__fmul_rn(R00, camx), __fmul_rn(R01, camy)),
                          __fmul_rn(R02, camz)), t0);
            const float py = __fadd_rn(
                __fadd_rn(__fadd_rn(__fmul_rn(R10, camx), __fmul_rn(R11, camy)),
                          __fmul_rn(R12, camz)), t1);
            const float pz = __fadd_rn(
                __fadd_rn(__fadd_rn(__fmul_rn(R20, camx), __fmul_rn(R21, camy)),
                          __fmul_rn(R22, camz)), t2);

            const int ix = __float2int_rd(px);
            const int iy = __float2int_rd(py);
            const int iz = __float2int_rd(pz);

            if (((unsigned)ix < DXV) & ((unsigned)iy < DYV) & ((unsigned)iz < DZV)) {
                const float v = __ldg(ob + ((iz * DYV + iy) * DXV + ix));
                hit = hit | (v != 0.0f);
            }
        }
        if (__all_sync(0xffffffffu, hit)) break;   // warp-converged early exit
    }

    out[((size_t)b * HH + h) * WW + w] = hit ? 1.0f : 0.0f;
}

extern "C" void kernel_launch(void* const* d_in, const int* in_sizes, int n_in,
                              void* d_out, int out_size)
{
    const float* occ  = (const float*)d_in[0];   // (8,1,128,128,256) f32
    const float* vm   = (const float*)d_in[1];   // (8,4,4) f32
    const float* intr = (const float*)d_in[2];   // (4,) f32
    float* out = (float*)d_out;                  // (8,1,256,320) f32

    dim3 block(32, 8, 1);
    dim3 grid(WW / 32, HH / 8, BB);              // 2560 CTAs
    raycast_occ_kernel<<<grid, block>>>(occ, vm, intr, out);
}

// round 6
// speedup vs baseline: 1.3030x; 1.3030x over previous
#include <cuda_runtime.h>
#include <cuda_bf16.h>

// RaycastOcc: out[b,0,h,w] = max over 120 steps of occ3d[b,0,iz,iy,ix],
// p = R@(dir*d)+t, idx = floor(p), bounds-masked. Bit-exact vs the jnp
// reference: every float op individually rounded (no fma contraction).
//
// Fast path (guarded, provably exact):
//  - off-diagonal R entries == 0.0f  =>  fl(0*c)=+-0 and fl(x+0)=x, so the
//    reduced chain px = fl(fl(R00*camx)+t0) is bit-identical.
//  - pz then thread-independent => per-step z offsets precomputed in smem.
//  - fl of a monotone affine chain is monotone in d => per-axis min/max at
//    endpoint steps; if endpoints in-bounds for the whole warp, drop all
//    bounds checks (identical results).

#define DZV 128
#define DYV 128
#define DXV 256
#define HH  256
#define WW  320
#define BB  8
#define NSTEP 120
#define DEPTH_MIN 0.1f
#define RAY_INC   0.02f

__device__ __forceinline__ float step_d(float kf) {
    return __fadd_rn(DEPTH_MIN, __fmul_rn(RAY_INC, kf));   // fl(0.1 + fl(0.02*k))
}

__global__ __launch_bounds__(256, 8)
void raycast_occ_kernel(const float* __restrict__ occ,
                        const float* __restrict__ vm,
                        const float* __restrict__ intr,
                        float* __restrict__ out)
{
    __shared__ int zoff_s[NSTEP];   // iz[k] * (DYV*DXV), diag fast path only

    const int w = blockIdx.x * 32 + threadIdx.x;
    const int h = blockIdx.y * 8  + threadIdx.y;
    const int b = blockIdx.z;
    const int tid = threadIdx.y * 32 + threadIdx.x;

    const float fx = __ldg(intr + 0);
    const float fy = __ldg(intr + 1);
    const float cx = __ldg(intr + 2);
    const float cy = __ldg(intr + 3);

    const float* M = vm + b * 16;
    const float R00 = __ldg(M + 0), R01 = __ldg(M + 1), R02 = __ldg(M + 2),  t0 = __ldg(M + 3);
    const float R10 = __ldg(M + 4), R11 = __ldg(M + 5), R12 = __ldg(M + 6),  t1 = __ldg(M + 7);
    const float R20 = __ldg(M + 8), R21 = __ldg(M + 9), R22 = __ldg(M + 10), t2 = __ldg(M + 11);

    const float dirx = __fdiv_rn(__fadd_rn(__fadd_rn((float)w, 0.5f), -cx), fx);
    const float diry = __fdiv_rn(__fadd_rn(__fadd_rn((float)h, 0.5f), -cy), fy);

    const float* ob = occ + (size_t)b * (DZV * DYV * DXV);

    // Grid-uniform: are all off-diagonal rotation terms exactly zero?
    const bool diag = (R01 == 0.0f) & (R02 == 0.0f) & (R10 == 0.0f) &
                      (R12 == 0.0f) & (R20 == 0.0f) & (R21 == 0.0f);

    float acc = 0.0f;

    if (diag) {
        // Precompute z offsets (thread-independent in diag case).
        if (tid < NSTEP) {
            const float d  = step_d((float)tid);
            const float pz = __fadd_rn(__fmul_rn(R22, d), t2);
            zoff_s[tid] = __float2int_rd(pz) * (DYV * DXV);
        }
        __syncthreads();

        // Endpoint bounds (monotone in d => extremes at k=0 and k=NSTEP-1).
        const float dA = step_d(0.0f), dB = step_d((float)(NSTEP - 1));
        const float pxA = __fadd_rn(__fmul_rn(R00, __fmul_rn(dirx, dA)), t0);
        const float pxB = __fadd_rn(__fmul_rn(R00, __fmul_rn(dirx, dB)), t0);
        const float pyA = __fadd_rn(__fmul_rn(R11, __fmul_rn(diry, dA)), t1);
        const float pyB = __fadd_rn(__fmul_rn(R11, __fmul_rn(diry, dB)), t1);
        const float pzA = __fadd_rn(__fmul_rn(R22, dA), t2);
        const float pzB = __fadd_rn(__fmul_rn(R22, dB), t2);
        const bool allv =
            (pxA >= 0.0f) & (pxA < (float)DXV) & (pxB >= 0.0f) & (pxB < (float)DXV) &
            (pyA >= 0.0f) & (pyA < (float)DYV) & (pyB >= 0.0f) & (pyB < (float)DYV) &
            (pzA >= 0.0f) & (pzA < (float)DZV) & (pzB >= 0.0f) & (pzB < (float)DZV);

        if (__all_sync(0xffffffffu, allv)) {
            // ---- fast path: no bounds checks, z from smem, d as immediates ----
            #pragma unroll
            for (int k = 0; k < NSTEP; ++k) {
                const float d  = step_d((float)k);              // constant-folded
                const float px = __fadd_rn(__fmul_rn(R00, __fmul_rn(dirx, d)), t0);
                const float py = __fadd_rn(__fmul_rn(R11, __fmul_rn(diry, d)), t1);
                const int ix = __float2int_rd(px);
                const int iy = __float2int_rd(py);
                const int off = zoff_s[k] + iy * DXV + ix;
                acc = fmaxf(acc, __ldg(ob + off));
                if ((k & 7) == 7) {
                    if (__all_sync(0xffffffffu, acc != 0.0f)) break;
                }
            }
            out[((size_t)b * HH + h) * WW + w] = acc;
            return;
        }
    }

    // ---- generic bit-exact fallback ----
    #pragma unroll 1
    for (int k0 = 0; k0 < NSTEP; k0 += 8) {
        const float kb = (float)k0;
        #pragma unroll
        for (int j = 0; j < 8; ++j) {
            const float kf = __fadd_rn(kb, (float)j);
            const float d  = step_d(kf);
            const float camx = __fmul_rn(dirx, d);
            const float camy = __fmul_rn(diry, d);
            const float camz = d;
            const float px = __fadd_rn(
                __fadd_rn(__fadd_rn(__fmul_rn(R00, camx), __fmul_rn(R01, camy)),
                          __fmul_rn(R02, camz)), t0);
            const float py = __fadd_rn(
                __fadd_rn(__fadd_rn(__fmul_rn(R10, camx), __fmul_rn(R11, camy)),
                          __fmul_rn(R12, camz)), t1);
            const float pz = __fadd_rn(
                __fadd_rn(__fadd_rn(__fmul_rn(R20, camx), __fmul_rn(R21, camy)),
                          __fmul_rn(R22, camz)), t2);
            const int ix = __float2int_rd(px);
            const int iy = __float2int_rd(py);
            const int iz = __float2int_rd(pz);
            if (((unsigned)ix < DXV) & ((unsigned)iy < DYV) & ((unsigned)iz < DZV)) {
                const float v = __ldg(ob + ((iz * DYV + iy) * DXV + ix));
                acc = fmaxf(acc, v);
            }
        }
        if (__all_sync(0xffffffffu, acc != 0.0f)) break;
    }

    out[((size_t)b * HH + h) * WW + w] = acc;
}

extern "C" void kernel_launch(void* const* d_in, const int* in_sizes, int n_in,
                              void* d_out, int out_size)
{
    const float* occ  = (const float*)d_in[0];   // (8,1,128,128,256) f32
    const float* vm   = (const float*)d_in[1];   // (8,4,4) f32
    const float* intr = (const float*)d_in[2];   // (4,) f32
    float* out = (float*)d_out;                  // (8,1,256,320) f32

    dim3 block(32, 8, 1);
    dim3 grid(WW / 32, HH / 8, BB);              // 2560 CTAs
    raycast_occ_kernel<<<grid, block>>>(occ, vm, intr, out);
}